// round 5
// baseline (speedup 1.0000x reference)
#include <cuda_runtime.h>
#include <cstdint>

// Depthwise 3D conv 3x3x3, SAME, stride 1.
// x: (N=4, D=16, H=112, W=112, C=64) f32, NDHWC
// w: (3,3,3,1,64) f32 -> idx ((kd*3+kh)*3+kw)*64 + c
//
// Thread: 2 channels (f32x2), 8 w-outputs, 2 h-rows.
// R5 change vs R4: explicit double-buffered row pipeline — row r+1's 10 loads
// issue before row r's 48 packed FMAs, forcing real MLP in SASS (ptxas kept
// collapsing the single-buffer preload back to 64 regs).

#define N_  4
#define D_  16
#define H_  112
#define W_  112
#define C_  64
#define WPT 8
#define CS  (C_ / 2)   // 32 ull per spatial position

typedef unsigned long long ull;

__device__ __forceinline__ ull ffma2(ull a, ull b, ull c) {
    ull d;
    asm("fma.rn.f32x2 %0, %1, %2, %3;" : "=l"(d) : "l"(a), "l"(b), "l"(c));
    return d;
}

// Load one full window row (zw = w0-1 .. w0+8) into buf[10].
// valid=false -> predicated off (no memory access), buf left as zeros.
__device__ __forceinline__ void load_row(ull* buf, const ull* __restrict__ p,
                                         bool valid, bool wlo, bool whi) {
    buf[0] = (valid && wlo) ? p[-CS] : 0ull;
#pragma unroll
    for (int j = 0; j < WPT; j++)
        buf[j + 1] = valid ? p[j * CS] : 0ull;
    buf[WPT + 1] = (valid && whi) ? p[WPT * CS] : 0ull;
}

__global__ void __launch_bounds__(128, 1)
dwconv3d_kernel(const float* __restrict__ x,
                const float* __restrict__ wgt,
                float* __restrict__ out) {
    __shared__ float swf[27 * C_];

    const int tid = threadIdx.y * 32 + threadIdx.x;
    for (int i = tid; i < 27 * C_ / 4; i += 128)
        reinterpret_cast<float4*>(swf)[i] =
            reinterpret_cast<const float4*>(wgt)[i];
    __syncthreads();

    const ull* __restrict__ swp = reinterpret_cast<const ull*>(swf);

    const int tx = threadIdx.x;                       // channel pair 0..31
    const int h0 = blockIdx.y * 8 + threadIdx.y * 2;  // even rows 0..110
    const int w0 = blockIdx.x * WPT;                  // 0..104
    const int nd = blockIdx.z;
    const int n  = nd >> 4;
    const int d  = nd & 15;

    const bool wlo = (w0 > 0);
    const bool whi = (w0 + WPT < W_);

    ull acc0[WPT], acc1[WPT];
#pragma unroll
    for (int i = 0; i < WPT; i++) { acc0[i] = 0ull; acc1[i] = 0ull; }

    const ull* __restrict__ xp = reinterpret_cast<const ull*>(x);

#pragma unroll
    for (int kd = 0; kd < 3; kd++) {
        const int zd = d + kd - 1;
        if ((unsigned)zd >= D_) continue;

        // pointer to (n, zd, h0-1, w0, tx)
        const ull* rowp =
            xp + ((((n * D_ + zd) * H_ + (h0 - 1)) * W_ + w0) * CS + tx);

        // weight rotation: wa = taps (kd, kh=r), wb = (kd, kh=r-1)
        ull wa0 = 0, wa1 = 0, wa2 = 0;
        ull wb0, wb1, wb2;

        ull buf[2][WPT + 2];

        // prime the pipeline: row r=0 (zh = h0-1)
        load_row(buf[0], rowp, h0 >= 1, wlo, whi);

#pragma unroll
        for (int r = 0; r < 4; r++) {          // zh = h0-1+r
            wb0 = wa0; wb1 = wa1; wb2 = wa2;
            if (r < 3) {
                const int base = (kd * 9 + r * 3) * CS + tx;
                wa0 = swp[base];
                wa1 = swp[base + CS];
                wa2 = swp[base + 2 * CS];
            }

            // prefetch next row into the other buffer BEFORE this row's FMAs
            if (r < 3)
                load_row(buf[(r + 1) & 1], rowp + W_ * CS,
                         (h0 + r) < H_, wlo, whi);

            const int zh = h0 - 1 + r;
            if ((unsigned)zh < H_) {
                const ull* rv = buf[r & 1];
#pragma unroll
                for (int i = 0; i < WPT; i++) {
                    if (r <= 2) {                          // output h0, kh=r
                        acc0[i] = ffma2(rv[i],     wa0, acc0[i]);
                        acc0[i] = ffma2(rv[i + 1], wa1, acc0[i]);
                        acc0[i] = ffma2(rv[i + 2], wa2, acc0[i]);
                    }
                    if (r >= 1) {                          // output h0+1, kh=r-1
                        acc1[i] = ffma2(rv[i],     wb0, acc1[i]);
                        acc1[i] = ffma2(rv[i + 1], wb1, acc1[i]);
                        acc1[i] = ffma2(rv[i + 2], wb2, acc1[i]);
                    }
                }
            }
            rowp += W_ * CS;
        }
    }

    ull* __restrict__ op =
        reinterpret_cast<ull*>(out) +
        ((((n * D_ + d) * H_ + h0) * W_ + w0) * CS + tx);
#pragma unroll
    for (int i = 0; i < WPT; i++) {
        op[i * CS] = acc0[i];
        op[W_ * CS + i * CS] = acc1[i];
    }
}

extern "C" void kernel_launch(void* const* d_in, const int* in_sizes, int n_in,
                              void* d_out, int out_size) {
    const float* x = (const float*)d_in[0];
    const float* w = (const float*)d_in[1];
    float* o = (float*)d_out;

    dim3 block(32, 4, 1);                        // 128 threads
    dim3 grid(W_ / WPT, H_ / 8, N_ * D_);        // 14 x 14 x 64
    dwconv3d_kernel<<<grid, block>>>(x, w, o);
}

// round 6
// speedup vs baseline: 1.1832x; 1.1832x over previous
#include <cuda_runtime.h>
#include <cstdint>

// Depthwise 3D conv 3x3x3, SAME, stride 1.
// x: (N=4, D=16, H=112, W=112, C=64) f32, NDHWC
// w: (3,3,3,1,64) f32 -> idx ((kd*3+kh)*3+kw)*64 + c
//
// Thread: 2 channels (f32x2), 8 w-outputs, 2 h-rows.
// R6 vs R4/R5: pinned register budget via __launch_bounds__(128, 6) (<=85
// regs) so the batched rv[10] row preload stays live in SASS (R4: ptxas
// clamped to 64 and serialized it; R5: uncapped ballooned to 138 regs and
// occupancy collapsed). Row schedule: 10 LDG -> 3 LDS -> 48 packed FMA.

#define N_  4
#define D_  16
#define H_  112
#define W_  112
#define C_  64
#define WPT 8
#define CS  (C_ / 2)   // 32 ull per spatial position

typedef unsigned long long ull;

__device__ __forceinline__ ull ffma2(ull a, ull b, ull c) {
    ull d;
    asm("fma.rn.f32x2 %0, %1, %2, %3;" : "=l"(d) : "l"(a), "l"(b), "l"(c));
    return d;
}

__global__ void __launch_bounds__(128, 6)
dwconv3d_kernel(const float* __restrict__ x,
                const float* __restrict__ wgt,
                float* __restrict__ out) {
    __shared__ float swf[27 * C_];

    const int tid = threadIdx.y * 32 + threadIdx.x;
    for (int i = tid; i < 27 * C_ / 4; i += 128)
        reinterpret_cast<float4*>(swf)[i] =
            reinterpret_cast<const float4*>(wgt)[i];
    __syncthreads();

    const ull* __restrict__ swp = reinterpret_cast<const ull*>(swf);

    const int tx = threadIdx.x;                       // channel pair 0..31
    const int h0 = blockIdx.y * 8 + threadIdx.y * 2;  // even rows 0..110
    const int w0 = blockIdx.x * WPT;                  // 0..104
    const int nd = blockIdx.z;
    const int n  = nd >> 4;
    const int d  = nd & 15;

    const bool wlo = (w0 > 0);
    const bool whi = (w0 + WPT < W_);   // zw = w0+8 in range?

    ull acc0[WPT], acc1[WPT];
#pragma unroll
    for (int i = 0; i < WPT; i++) { acc0[i] = 0ull; acc1[i] = 0ull; }

    const ull* __restrict__ xp = reinterpret_cast<const ull*>(x);

#pragma unroll
    for (int kd = 0; kd < 3; kd++) {
        const int zd = d + kd - 1;
        if ((unsigned)zd >= D_) continue;

        // pointer to (n, zd, h0-1, w0, tx); advances one h-row per r
        const ull* rowp =
            xp + ((((n * D_ + zd) * H_ + (h0 - 1)) * W_ + w0) * CS + tx);

        // weight rotation: wa = taps (kd, kh=r), wb = (kd, kh=r-1)
        ull wa0 = 0, wa1 = 0, wa2 = 0;
        ull wb0, wb1, wb2;

#pragma unroll
        for (int r = 0; r < 4; r++) {          // zh = h0-1 .. h0+2
            const int zh = h0 - 1 + r;
            if ((unsigned)zh < H_) {
                const ull* __restrict__ p = rowp;

                // --- batched row preload first: 10 independent LDGs ---
                ull rv[WPT + 2];
                rv[0] = wlo ? p[-CS] : 0ull;
#pragma unroll
                for (int j = 0; j < WPT; j++)
                    rv[j + 1] = p[j * CS];
                rv[WPT + 1] = whi ? p[WPT * CS] : 0ull;

                // --- weight rotate + fetch (LDS drains under LDG latency) ---
                wb0 = wa0; wb1 = wa1; wb2 = wa2;
                if (r < 3) {
                    const int base = (kd * 9 + r * 3) * CS + tx;
                    wa0 = swp[base];
                    wa1 = swp[base + CS];
                    wa2 = swp[base + 2 * CS];
                }

                // --- register-only FMA burst ---
#pragma unroll
                for (int i = 0; i < WPT; i++) {
                    if (r <= 2) {                          // output h0, kh=r
                        acc0[i] = ffma2(rv[i],     wa0, acc0[i]);
                        acc0[i] = ffma2(rv[i + 1], wa1, acc0[i]);
                        acc0[i] = ffma2(rv[i + 2], wa2, acc0[i]);
                    }
                    if (r >= 1) {                          // output h0+1, kh=r-1
                        acc1[i] = ffma2(rv[i],     wb0, acc1[i]);
                        acc1[i] = ffma2(rv[i + 1], wb1, acc1[i]);
                        acc1[i] = ffma2(rv[i + 2], wb2, acc1[i]);
                    }
                }
            } else {
                // row out of range: still rotate weights to keep tap alignment
                wb0 = wa0; wb1 = wa1; wb2 = wa2;
                if (r < 3) {
                    const int base = (kd * 9 + r * 3) * CS + tx;
                    wa0 = swp[base];
                    wa1 = swp[base + CS];
                    wa2 = swp[base + 2 * CS];
                }
            }
            rowp += W_ * CS;
        }
    }

    ull* __restrict__ op =
        reinterpret_cast<ull*>(out) +
        ((((n * D_ + d) * H_ + h0) * W_ + w0) * CS + tx);
#pragma unroll
    for (int i = 0; i < WPT; i++) {
        op[i * CS] = acc0[i];
        op[W_ * CS + i * CS] = acc1[i];
    }
}

extern "C" void kernel_launch(void* const* d_in, const int* in_sizes, int n_in,
                              void* d_out, int out_size) {
    const float* x = (const float*)d_in[0];
    const float* w = (const float*)d_in[1];
    float* o = (float*)d_out;

    dim3 block(32, 4, 1);                        // 128 threads
    dim3 grid(W_ / WPT, H_ / 8, N_ * D_);        // 14 x 14 x 64
    dwconv3d_kernel<<<grid, block>>>(x, w, o);
}